// round 2
// baseline (speedup 1.0000x reference)
#include <cuda_runtime.h>
#include <math.h>

#define BSZ    128
#define MAXLEN 256
#define DCHAR  256
#define DHID   1024
#define VOC    512
#define BT     (BSZ * MAXLEN)   // 32768
#define BH     (BSZ * DHID)     // 131072

// Scratch (allocation-free: __device__ globals)
__device__ float g_xp_enc[BT * DHID];   // 128 MB: enc input projections [B*T, H] (row=b*T+t)
__device__ float g_xp_dec[BT * DHID];   // 128 MB: dec input projections
__device__ float g_states[BT * DHID];   // 128 MB: decoder hidden states, row=b*T+t
__device__ float g_h[2 * BH];           // ping-pong hidden for encoder

// ---------------------------------------------------------------------------
// Generic tiled SGEMM with row gather:
//   C[row, n] = sum_k A[src(row), k] * B[n, k]  + bias1[n] (+ bias2[n])
// gmode 0: src = row (A is dense [M, lda])
// gmode 1: src = tokens[row]                (embedding gather)
// gmode 2: src = (row%T==0) ? -1 : tokens[row-1]  (teacher-forced dec input; -1 => zero row)
// ---------------------------------------------------------------------------
#define GBM 64
#define GBN 64
#define GBK 16

__global__ void gemm_gather_kernel(const float* __restrict__ A, int lda,
                                   const int* __restrict__ tokens, int gmode, int T,
                                   const float* __restrict__ B,     // [N, K] row-major
                                   const float* __restrict__ bias1,
                                   const float* __restrict__ bias2,
                                   float* __restrict__ C,
                                   int N, int K)
{
    __shared__ __align__(16) float As[GBK][GBM + 4];
    __shared__ __align__(16) float Bs[GBK][GBN + 4];
    __shared__ int rowsrc[GBM];

    const int bm  = blockIdx.y * GBM;
    const int bn  = blockIdx.x * GBN;
    const int tid = threadIdx.x;   // 256 threads

    if (tid < GBM) {
        int row = bm + tid;
        int src = row;
        if (gmode == 1) {
            src = tokens[row];
        } else if (gmode == 2) {
            int t = row % T;
            src = (t == 0) ? -1 : tokens[row - 1];
        }
        rowsrc[tid] = src;
    }
    __syncthreads();

    const int tm = (tid >> 4) * 4;   // 0..60
    const int tn = (tid & 15) * 4;   // 0..60

    float acc[4][4] = {};

    for (int k0 = 0; k0 < K; k0 += GBK) {
        #pragma unroll
        for (int i = 0; i < 4; i++) {
            int idx = tid + i * 256;
            int m = idx >> 4, kk = idx & 15;
            int src = rowsrc[m];
            As[kk][m] = (src < 0) ? 0.0f : A[src * lda + k0 + kk];
        }
        #pragma unroll
        for (int i = 0; i < 4; i++) {
            int idx = tid + i * 256;
            int n = idx >> 4, kk = idx & 15;
            Bs[kk][n] = B[(bn + n) * K + k0 + kk];
        }
        __syncthreads();

        #pragma unroll
        for (int kk = 0; kk < GBK; kk++) {
            float4 a = *reinterpret_cast<const float4*>(&As[kk][tm]);
            float4 b = *reinterpret_cast<const float4*>(&Bs[kk][tn]);
            acc[0][0] += a.x * b.x; acc[0][1] += a.x * b.y; acc[0][2] += a.x * b.z; acc[0][3] += a.x * b.w;
            acc[1][0] += a.y * b.x; acc[1][1] += a.y * b.y; acc[1][2] += a.y * b.z; acc[1][3] += a.y * b.w;
            acc[2][0] += a.z * b.x; acc[2][1] += a.z * b.y; acc[2][2] += a.z * b.z; acc[2][3] += a.z * b.w;
            acc[3][0] += a.w * b.x; acc[3][1] += a.w * b.y; acc[3][2] += a.w * b.z; acc[3][3] += a.w * b.w;
        }
        __syncthreads();
    }

    #pragma unroll
    for (int j = 0; j < 4; j++) {
        int n = bn + tn + j;
        float bb = (bias1 ? bias1[n] : 0.0f) + (bias2 ? bias2[n] : 0.0f);
        #pragma unroll
        for (int i = 0; i < 4; i++) {
            C[(bm + tm + i) * N + n] = acc[i][j] + bb;
        }
    }
}

// ---------------------------------------------------------------------------
// One recurrent step: h_out[b, n] = tanh( xp[b, n] + sum_k h_in[b, k] * Whh[n, k] )
// M = BSZ = 128, N = K = DHID = 1024. Tile [32 x 32], 128 CTAs, 128 threads.
// Row strides passed in so dec can read/write the strided states buffer.
// ---------------------------------------------------------------------------
#define RBM 32
#define RBN 32
#define RBK 16

__global__ void rnn_step_kernel(const float* __restrict__ h_in, int h_in_stride,
                                const float* __restrict__ xp, int xp_stride,
                                const float* __restrict__ Whh,   // [DHID, DHID]
                                float* __restrict__ h_out, int h_out_stride)
{
    __shared__ __align__(16) float As[RBK][RBM + 2];   // row stride 34 floats (136 B, 8B-aligned)
    __shared__ __align__(16) float Bs[RBK][RBN + 4];   // row stride 36 floats (144 B, 16B-aligned)

    const int bm  = blockIdx.y * RBM;   // batch offset
    const int bn  = blockIdx.x * RBN;   // hidden-out offset
    const int tid = threadIdx.x;        // 128 threads
    const int tmi = tid >> 3;           // 0..15 (pairs of batch rows)
    const int tni = tid & 7;            // 0..7  (quads of hidden cols)

    float acc[2][4] = {};

    for (int k0 = 0; k0 < DHID; k0 += RBK) {
        #pragma unroll
        for (int i = 0; i < 4; i++) {
            int idx = tid + i * 128;
            int m = idx >> 4, kk = idx & 15;
            As[kk][m] = h_in[(bm + m) * h_in_stride + k0 + kk];
        }
        #pragma unroll
        for (int i = 0; i < 4; i++) {
            int idx = tid + i * 128;
            int n = idx >> 4, kk = idx & 15;
            Bs[kk][n] = Whh[(bn + n) * DHID + k0 + kk];
        }
        __syncthreads();

        #pragma unroll
        for (int kk = 0; kk < RBK; kk++) {
            float2 a = *reinterpret_cast<const float2*>(&As[kk][tmi * 2]);
            float4 b = *reinterpret_cast<const float4*>(&Bs[kk][tni * 4]);
            acc[0][0] += a.x * b.x; acc[0][1] += a.x * b.y; acc[0][2] += a.x * b.z; acc[0][3] += a.x * b.w;
            acc[1][0] += a.y * b.x; acc[1][1] += a.y * b.y; acc[1][2] += a.y * b.z; acc[1][3] += a.y * b.w;
        }
        __syncthreads();
    }

    #pragma unroll
    for (int i = 0; i < 2; i++) {
        int b = bm + tmi * 2 + i;
        #pragma unroll
        for (int j = 0; j < 4; j++) {
            int n = bn + tni * 4 + j;
            float v = tanhf(acc[i][j] + xp[b * xp_stride + n]);
            h_out[b * h_out_stride + n] = v;
        }
    }
}

// ---------------------------------------------------------------------------
// In-place row-wise log-softmax over VOC=512 columns. One warp per row.
// ---------------------------------------------------------------------------
__global__ void log_softmax_kernel(float* __restrict__ data)
{
    int gw   = (blockIdx.x * blockDim.x + threadIdx.x) >> 5;
    int lane = threadIdx.x & 31;
    if (gw >= BT) return;
    float* row = data + (size_t)gw * VOC;

    float v[16];
    float mx = -1e30f;
    #pragma unroll
    for (int i = 0; i < 16; i++) {
        v[i] = row[lane + i * 32];
        mx = fmaxf(mx, v[i]);
    }
    #pragma unroll
    for (int o = 16; o > 0; o >>= 1)
        mx = fmaxf(mx, __shfl_xor_sync(0xffffffffu, mx, o));

    float s = 0.0f;
    #pragma unroll
    for (int i = 0; i < 16; i++) s += expf(v[i] - mx);
    #pragma unroll
    for (int o = 16; o > 0; o >>= 1)
        s += __shfl_xor_sync(0xffffffffu, s, o);

    float lse = mx + logf(s);
    #pragma unroll
    for (int i = 0; i < 16; i++) row[lane + i * 32] = v[i] - lse;
}

// ---------------------------------------------------------------------------
extern "C" void kernel_launch(void* const* d_in, const int* in_sizes, int n_in,
                              void* d_out, int out_size)
{
    const int*   inputs  = (const int*)d_in[0];
    const int*   outputs = (const int*)d_in[1];
    const float* emb     = (const float*)d_in[2];
    const float* enc_Wih = (const float*)d_in[3];
    const float* enc_Whh = (const float*)d_in[4];
    const float* enc_bih = (const float*)d_in[5];
    const float* enc_bhh = (const float*)d_in[6];
    const float* dec_Wih = (const float*)d_in[7];
    const float* dec_Whh = (const float*)d_in[8];
    const float* dec_bih = (const float*)d_in[9];
    const float* dec_bhh = (const float*)d_in[10];
    const float* out_W   = (const float*)d_in[11];
    const float* out_b   = (const float*)d_in[12];
    float* out = (float*)d_out;

    float *xp_enc, *xp_dec, *states, *hbuf;
    cudaGetSymbolAddress((void**)&xp_enc, g_xp_enc);
    cudaGetSymbolAddress((void**)&xp_dec, g_xp_dec);
    cudaGetSymbolAddress((void**)&states, g_states);
    cudaGetSymbolAddress((void**)&hbuf,   g_h);

    // Input projections (embedding gather fused into GEMM A-tile load).
    // xp = emb[tok] @ Wih^T + bih + bhh   -> [B*T, H]
    gemm_gather_kernel<<<dim3(DHID / GBN, BT / GBM), 256>>>(
        emb, DCHAR, inputs, 1, MAXLEN, enc_Wih, enc_bih, enc_bhh, xp_enc, DHID, DCHAR);
    gemm_gather_kernel<<<dim3(DHID / GBN, BT / GBM), 256>>>(
        emb, DCHAR, outputs, 2, MAXLEN, dec_Wih, dec_bih, dec_bhh, xp_dec, DHID, DCHAR);

    // h0 = 0
    cudaMemsetAsync(hbuf, 0, BH * sizeof(float));

    dim3 rgrid(DHID / RBN, BSZ / RBM);   // (32, 4) = 128 CTAs

    // Encoder scan: ping-pong hidden buffers. hT lands in hbuf (T even).
    for (int t = 0; t < MAXLEN; t++) {
        const float* hin  = hbuf + (t & 1) * BH;
        float*       hout = hbuf + ((t + 1) & 1) * BH;
        rnn_step_kernel<<<rgrid, 128>>>(hin, DHID,
                                        xp_enc + t * DHID, MAXLEN * DHID,
                                        enc_Whh,
                                        hout, DHID);
    }

    // Decoder scan: write directly into states[b*T + t, :] (stride T*H).
    for (int t = 0; t < MAXLEN; t++) {
        const float* hin     = (t == 0) ? hbuf : (states + (t - 1) * DHID);
        int          hstride = (t == 0) ? DHID : MAXLEN * DHID;
        rnn_step_kernel<<<rgrid, 128>>>(hin, hstride,
                                        xp_dec + t * DHID, MAXLEN * DHID,
                                        dec_Whh,
                                        states + t * DHID, MAXLEN * DHID);
    }

    // logits = states @ out_W^T + out_b -> write straight into d_out, softmax in place.
    gemm_gather_kernel<<<dim3(VOC / GBN, BT / GBM), 256>>>(
        states, DHID, nullptr, 0, MAXLEN, out_W, out_b, nullptr, out, VOC, DHID);

    log_softmax_kernel<<<BT / 8, 256>>>(out);
}

// round 3
// speedup vs baseline: 1.8112x; 1.8112x over previous
#include <cuda_runtime.h>
#include <math.h>

#define BSZ    128
#define MAXLEN 256
#define DCHAR  256
#define DHID   1024
#define VOC    512
#define BT     (BSZ * MAXLEN)   // 32768
#define BH     (BSZ * DHID)     // 131072

// ---------------------------------------------------------------------------
// Scratch (allocation-free: __device__ globals)
// ---------------------------------------------------------------------------
__device__ float g_xp_enc[BT * DHID];   // enc input projections [b*T+t, n]
__device__ float g_xp_dec[BT * DHID];   // dec input projections
__device__ float g_states[BT * DHID];   // decoder hidden states [b*T+t, n]
__device__ float g_hT0[DHID * BSZ];     // transposed hidden ping [k][b]
__device__ float g_hT1[DHID * BSZ];     // transposed hidden pong [k][b]

__device__ unsigned g_bar_cnt   = 0;    // grid barrier arrive counter (self-resetting)
__device__ unsigned g_bar_phase = 0;    // grid barrier phase (monotone, wrap-safe)

// ---------------------------------------------------------------------------
// Generic tiled SGEMM with row gather (unchanged from R2):
//   C[row, n] = sum_k A[src(row), k] * B[n, k] + bias1[n] (+ bias2[n])
// ---------------------------------------------------------------------------
#define GBM 64
#define GBN 64
#define GBK 16

__global__ void gemm_gather_kernel(const float* __restrict__ A, int lda,
                                   const int* __restrict__ tokens, int gmode, int T,
                                   const float* __restrict__ B,
                                   const float* __restrict__ bias1,
                                   const float* __restrict__ bias2,
                                   float* __restrict__ C,
                                   int N, int K)
{
    __shared__ __align__(16) float As[GBK][GBM + 4];
    __shared__ __align__(16) float Bs[GBK][GBN + 4];
    __shared__ int rowsrc[GBM];

    const int bm  = blockIdx.y * GBM;
    const int bn  = blockIdx.x * GBN;
    const int tid = threadIdx.x;

    if (tid < GBM) {
        int row = bm + tid;
        int src = row;
        if (gmode == 1) {
            src = tokens[row];
        } else if (gmode == 2) {
            int t = row % T;
            src = (t == 0) ? -1 : tokens[row - 1];
        }
        rowsrc[tid] = src;
    }
    __syncthreads();

    const int tm = (tid >> 4) * 4;
    const int tn = (tid & 15) * 4;

    float acc[4][4] = {};

    for (int k0 = 0; k0 < K; k0 += GBK) {
        #pragma unroll
        for (int i = 0; i < 4; i++) {
            int idx = tid + i * 256;
            int m = idx >> 4, kk = idx & 15;
            int src = rowsrc[m];
            As[kk][m] = (src < 0) ? 0.0f : A[src * lda + k0 + kk];
        }
        #pragma unroll
        for (int i = 0; i < 4; i++) {
            int idx = tid + i * 256;
            int n = idx >> 4, kk = idx & 15;
            Bs[kk][n] = B[(bn + n) * K + k0 + kk];
        }
        __syncthreads();

        #pragma unroll
        for (int kk = 0; kk < GBK; kk++) {
            float4 a = *reinterpret_cast<const float4*>(&As[kk][tm]);
            float4 b = *reinterpret_cast<const float4*>(&Bs[kk][tn]);
            acc[0][0] += a.x * b.x; acc[0][1] += a.x * b.y; acc[0][2] += a.x * b.z; acc[0][3] += a.x * b.w;
            acc[1][0] += a.y * b.x; acc[1][1] += a.y * b.y; acc[1][2] += a.y * b.z; acc[1][3] += a.y * b.w;
            acc[2][0] += a.z * b.x; acc[2][1] += a.z * b.y; acc[2][2] += a.z * b.z; acc[2][3] += a.z * b.w;
            acc[3][0] += a.w * b.x; acc[3][1] += a.w * b.y; acc[3][2] += a.w * b.z; acc[3][3] += a.w * b.w;
        }
        __syncthreads();
    }

    #pragma unroll
    for (int j = 0; j < 4; j++) {
        int n = bn + tn + j;
        float bb = (bias1 ? bias1[n] : 0.0f) + (bias2 ? bias2[n] : 0.0f);
        #pragma unroll
        for (int i = 0; i < 4; i++) {
            C[(bm + tm + i) * N + n] = acc[i][j] + bb;
        }
    }
}

// ---------------------------------------------------------------------------
// Persistent recurrence kernel.
// Grid (32, 4) = 128 CTAs (co-resident: 1 CTA/SM, 128 <= 148). 128 threads.
// CTA (ni, mi) owns output tile b in [32*mi, +32), n in [32*ni, +32).
// Whh slice [32n x 1024k] resident in smem as Ws[k][n] (stride 34, padded).
// h ping-pongs through g_hT0/g_hT1 in transposed layout h_T[k][b].
// Per step: stage h-tile [128k x 32b] chunks into smem (double-buffered),
// FFMA2 (fma.rn.f32x2) inner product, tanh(acc + xp), write h_T (+ states).
// ---------------------------------------------------------------------------
#define KC       128                   // k-chunk
#define NCTA     128
#define WS_STRIDE 34                   // padded row stride of Ws (even -> 8B aligned)
#define SMEM_FLOATS (DHID * WS_STRIDE + 2 * KC * 32)
#define SMEM_BYTES  (SMEM_FLOATS * 4)  // 172032 B

__device__ __forceinline__ void load_whh_slice(float* Ws, const float* __restrict__ W,
                                               int ntile, int tid)
{
    // W row-major [DHID n][DHID k]; load rows ntile..ntile+31 transposed into Ws[k][n].
    for (int idx = tid; idx < 32 * 256; idx += 128) {
        int row = idx >> 8;          // 0..31 (n local)
        int c4  = idx & 255;         // 0..255 (k/4)
        float4 v = *reinterpret_cast<const float4*>(&W[(ntile + row) * DHID + c4 * 4]);
        int k = c4 * 4;
        Ws[(k + 0) * WS_STRIDE + row] = v.x;
        Ws[(k + 1) * WS_STRIDE + row] = v.y;
        Ws[(k + 2) * WS_STRIDE + row] = v.z;
        Ws[(k + 3) * WS_STRIDE + row] = v.w;
    }
}

__device__ __forceinline__ void grid_barrier(unsigned target)
{
    __syncthreads();
    if (threadIdx.x == 0) {
        __threadfence();
        unsigned arrived = atomicAdd(&g_bar_cnt, 1u);
        if (arrived == NCTA - 1) {
            atomicExch(&g_bar_cnt, 0u);
            __threadfence();
            atomicAdd(&g_bar_phase, 1u);
        } else {
            while ((int)(atomicAdd(&g_bar_phase, 0u) - target) < 0)
                __nanosleep(40);
        }
        __threadfence();
    }
    __syncthreads();
}

__global__ void __launch_bounds__(128, 1)
rnn_persistent_kernel(const float* __restrict__ xp_enc,
                      const float* __restrict__ xp_dec,
                      const float* __restrict__ enc_Whh,
                      const float* __restrict__ dec_Whh,
                      float* __restrict__ states,
                      float* __restrict__ hT0,
                      float* __restrict__ hT1)
{
    extern __shared__ float sm[];
    float* Ws = sm;                       // [1024][34]
    float* hsb = sm + DHID * WS_STRIDE;   // 2 x [KC][32]

    const int tid = threadIdx.x;
    const int ni = blockIdx.x, mi = blockIdx.y;
    const int btile = mi * 32, ntile = ni * 32;
    const int w = tid >> 5, l = tid & 31;
    const int jj = l >> 3;                // 0..3
    const int q  = l & 7;                 // 0..7
    const int n_local = w * 8 + jj * 2;   // 2 columns
    const int b_local = q * 4;            // 4 batch rows

    // Read barrier phase baseline (uniform: no CTA can pass a barrier until all arrive).
    __shared__ unsigned s_ph;
    if (tid == 0) s_ph = atomicAdd(&g_bar_phase, 0u);

    // Zero h0 (ping buffer).
    {
        const int cta = mi * gridDim.x + ni;
        float4 z = make_float4(0.f, 0.f, 0.f, 0.f);
        *reinterpret_cast<float4*>(&hT0[cta * 1024 + tid * 8])     = z;
        *reinterpret_cast<float4*>(&hT0[cta * 1024 + tid * 8 + 4]) = z;
    }
    __syncthreads();
    unsigned target = s_ph;

    load_whh_slice(Ws, enc_Whh, ntile, tid);

    target++; grid_barrier(target);   // h0 + Whh visible everywhere

    const int rrow = tid >> 3;            // staging row base
    const int rcol = (tid & 7) * 4;       // staging col

    for (int s = 0; s < 512; s++) {
        if (s == 256) {
            load_whh_slice(Ws, dec_Whh, ntile, tid);
            __syncthreads();
        }
        const float* __restrict__ hin  = (s & 1) ? hT1 : hT0;
        float* __restrict__       hout = (s & 1) ? hT0 : hT1;
        const int t = s & 255;
        const float* __restrict__ xp = (s < 256) ? xp_enc : xp_dec;

        unsigned long long acc00 = 0ull, acc01 = 0ull, acc10 = 0ull, acc11 = 0ull;

        // Prologue: stage chunk 0.
        float4 r[8];
        #pragma unroll
        for (int i = 0; i < 8; i++)
            r[i] = *reinterpret_cast<const float4*>(&hin[(rrow + i * 16) * BSZ + btile + rcol]);
        #pragma unroll
        for (int i = 0; i < 8; i++)
            *reinterpret_cast<float4*>(&hsb[(rrow + i * 16) * 32 + rcol]) = r[i];
        __syncthreads();

        #pragma unroll 1
        for (int c = 0; c < 8; c++) {
            const int cb = c & 1;
            // Prefetch next chunk into registers (LDG latency hidden by compute).
            if (c < 7) {
                #pragma unroll
                for (int i = 0; i < 8; i++)
                    r[i] = *reinterpret_cast<const float4*>(
                        &hin[((c + 1) * KC + rrow + i * 16) * BSZ + btile + rcol]);
            }
            const float* hp = &hsb[cb * KC * 32 + b_local];
            const float* wp = &Ws[(c * KC) * WS_STRIDE + n_local];
            #pragma unroll 4
            for (int kk = 0; kk < KC; kk++) {
                float4 h4 = *reinterpret_cast<const float4*>(hp + kk * 32);
                float2 w2 = *reinterpret_cast<const float2*>(wp + kk * WS_STRIDE);
                unsigned long long h01, h23, w00, w11;
                asm("mov.b64 %0,{%1,%2};" : "=l"(h01) : "f"(h4.x), "f"(h4.y));
                asm("mov.b64 %0,{%1,%2};" : "=l"(h23) : "f"(h4.z), "f"(h4.w));
                asm("mov.b64 %0,{%1,%1};" : "=l"(w00) : "f"(w2.x));
                asm("mov.b64 %0,{%1,%1};" : "=l"(w11) : "f"(w2.y));
                asm("fma.rn.f32x2 %0,%1,%2,%0;" : "+l"(acc00) : "l"(h01), "l"(w00));
                asm("fma.rn.f32x2 %0,%1,%2,%0;" : "+l"(acc01) : "l"(h01), "l"(w11));
                asm("fma.rn.f32x2 %0,%1,%2,%0;" : "+l"(acc10) : "l"(h23), "l"(w00));
                asm("fma.rn.f32x2 %0,%1,%2,%0;" : "+l"(acc11) : "l"(h23), "l"(w11));
            }
            if (c < 7) {
                // hs[!cb] was last read in chunk c-1 (sync'ed) -> safe to overwrite.
                #pragma unroll
                for (int i = 0; i < 8; i++)
                    *reinterpret_cast<float4*>(&hsb[(1 - cb) * KC * 32 + (rrow + i * 16) * 32 + rcol]) = r[i];
                __syncthreads();
            }
        }

        // Epilogue: tanh(acc + xp), write transposed h (+ decoder states).
        float2 a[2][2];
        a[0][0] = *reinterpret_cast<float2*>(&acc00);
        a[0][1] = *reinterpret_cast<float2*>(&acc01);
        a[1][0] = *reinterpret_cast<float2*>(&acc10);
        a[1][1] = *reinterpret_cast<float2*>(&acc11);

        #pragma unroll
        for (int p = 0; p < 2; p++) {
            #pragma unroll
            for (int jn = 0; jn < 2; jn++) {
                int b0 = btile + b_local + p * 2;
                int n  = ntile + n_local + jn;
                float x0 = xp[((size_t)b0       * MAXLEN + t) * DHID + n];
                float x1 = xp[((size_t)(b0 + 1) * MAXLEN + t) * DHID + n];
                float h0 = tanhf(a[p][jn].x + x0);
                float h1 = tanhf(a[p][jn].y + x1);
                *reinterpret_cast<float2*>(&hout[n * BSZ + b0]) = make_float2(h0, h1);
                if (s >= 256) {
                    states[((size_t)b0       * MAXLEN + t) * DHID + n] = h0;
                    states[((size_t)(b0 + 1) * MAXLEN + t) * DHID + n] = h1;
                }
            }
        }

        target++; grid_barrier(target);
    }
}

// ---------------------------------------------------------------------------
// In-place row-wise log-softmax over VOC=512 columns. One warp per row.
// ---------------------------------------------------------------------------
__global__ void log_softmax_kernel(float* __restrict__ data)
{
    int gw   = (blockIdx.x * blockDim.x + threadIdx.x) >> 5;
    int lane = threadIdx.x & 31;
    if (gw >= BT) return;
    float* row = data + (size_t)gw * VOC;

    float v[16];
    float mx = -1e30f;
    #pragma unroll
    for (int i = 0; i < 16; i++) {
        v[i] = row[lane + i * 32];
        mx = fmaxf(mx, v[i]);
    }
    #pragma unroll
    for (int o = 16; o > 0; o >>= 1)
        mx = fmaxf(mx, __shfl_xor_sync(0xffffffffu, mx, o));

    float s = 0.0f;
    #pragma unroll
    for (int i = 0; i < 16; i++) s += expf(v[i] - mx);
    #pragma unroll
    for (int o = 16; o > 0; o >>= 1)
        s += __shfl_xor_sync(0xffffffffu, s, o);

    float lse = mx + logf(s);
    #pragma unroll
    for (int i = 0; i < 16; i++) row[lane + i * 32] = v[i] - lse;
}

// ---------------------------------------------------------------------------
extern "C" void kernel_launch(void* const* d_in, const int* in_sizes, int n_in,
                              void* d_out, int out_size)
{
    const int*   inputs  = (const int*)d_in[0];
    const int*   outputs = (const int*)d_in[1];
    const float* emb     = (const float*)d_in[2];
    const float* enc_Wih = (const float*)d_in[3];
    const float* enc_Whh = (const float*)d_in[4];
    const float* enc_bih = (const float*)d_in[5];
    const float* enc_bhh = (const float*)d_in[6];
    const float* dec_Wih = (const float*)d_in[7];
    const float* dec_Whh = (const float*)d_in[8];
    const float* dec_bih = (const float*)d_in[9];
    const float* dec_bhh = (const float*)d_in[10];
    const float* out_W   = (const float*)d_in[11];
    const float* out_b   = (const float*)d_in[12];
    float* out = (float*)d_out;

    float *xp_enc, *xp_dec, *states, *hT0, *hT1;
    cudaGetSymbolAddress((void**)&xp_enc, g_xp_enc);
    cudaGetSymbolAddress((void**)&xp_dec, g_xp_dec);
    cudaGetSymbolAddress((void**)&states, g_states);
    cudaGetSymbolAddress((void**)&hT0,    g_hT0);
    cudaGetSymbolAddress((void**)&hT1,    g_hT1);

    // Input projections (embedding gather fused): xp = emb[tok] @ Wih^T + bih + bhh
    gemm_gather_kernel<<<dim3(DHID / GBN, BT / GBM), 256>>>(
        emb, DCHAR, inputs, 1, MAXLEN, enc_Wih, enc_bih, enc_bhh, xp_enc, DHID, DCHAR);
    gemm_gather_kernel<<<dim3(DHID / GBN, BT / GBM), 256>>>(
        emb, DCHAR, outputs, 2, MAXLEN, dec_Wih, dec_bih, dec_bhh, xp_dec, DHID, DCHAR);

    // Persistent recurrence: encoder 256 steps + decoder 256 steps, grid-synced.
    cudaFuncSetAttribute(rnn_persistent_kernel,
                         cudaFuncAttributeMaxDynamicSharedMemorySize, SMEM_BYTES);
    rnn_persistent_kernel<<<dim3(32, 4), 128, SMEM_BYTES>>>(
        xp_enc, xp_dec, enc_Whh, dec_Whh, states, hT0, hT1);

    // logits = states @ out_W^T + out_b -> d_out, then log-softmax in place.
    gemm_gather_kernel<<<dim3(VOC / GBN, BT / GBM), 256>>>(
        states, DHID, nullptr, 0, MAXLEN, out_W, out_b, nullptr, out, VOC, DHID);

    log_softmax_kernel<<<BT / 8, 256>>>(out);
}

// round 4
// speedup vs baseline: 1.8137x; 1.0014x over previous
#include <cuda_runtime.h>
#include <math.h>

#define BSZ    128
#define MAXLEN 256
#define DCHAR  256
#define DHID   1024
#define VOC    512
#define BT     (BSZ * MAXLEN)   // 32768
#define BH     (BSZ * DHID)     // 131072

// ---------------------------------------------------------------------------
// Scratch (allocation-free: __device__ globals)
// ---------------------------------------------------------------------------
__device__ float g_xp_enc[BT * DHID];   // enc input projections [b*T+t, n]
__device__ float g_xp_dec[BT * DHID];   // dec input projections
__device__ float g_states[BT * DHID];   // decoder hidden states [b*T+t, n]
__device__ float g_hT0[DHID * BSZ];     // transposed hidden ping [k][b]
__device__ float g_hT1[DHID * BSZ];     // transposed hidden pong [k][b]

__device__ unsigned g_bar_cnt   = 0;    // grid barrier arrive counter (self-resetting)
__device__ unsigned g_bar_phase = 0;    // grid barrier phase (monotone, wrap-safe)

// ---------------------------------------------------------------------------
// Generic tiled SGEMM with row gather (unchanged from R2):
//   C[row, n] = sum_k A[src(row), k] * B[n, k] + bias1[n] (+ bias2[n])
// ---------------------------------------------------------------------------
#define GBM 64
#define GBN 64
#define GBK 16

__global__ void gemm_gather_kernel(const float* __restrict__ A, int lda,
                                   const int* __restrict__ tokens, int gmode, int T,
                                   const float* __restrict__ B,
                                   const float* __restrict__ bias1,
                                   const float* __restrict__ bias2,
                                   float* __restrict__ C,
                                   int N, int K)
{
    __shared__ __align__(16) float As[GBK][GBM + 4];
    __shared__ __align__(16) float Bs[GBK][GBN + 4];
    __shared__ int rowsrc[GBM];

    const int bm  = blockIdx.y * GBM;
    const int bn  = blockIdx.x * GBN;
    const int tid = threadIdx.x;

    if (tid < GBM) {
        int row = bm + tid;
        int src = row;
        if (gmode == 1) {
            src = tokens[row];
        } else if (gmode == 2) {
            int t = row % T;
            src = (t == 0) ? -1 : tokens[row - 1];
        }
        rowsrc[tid] = src;
    }
    __syncthreads();

    const int tm = (tid >> 4) * 4;
    const int tn = (tid & 15) * 4;

    float acc[4][4] = {};

    for (int k0 = 0; k0 < K; k0 += GBK) {
        #pragma unroll
        for (int i = 0; i < 4; i++) {
            int idx = tid + i * 256;
            int m = idx >> 4, kk = idx & 15;
            int src = rowsrc[m];
            As[kk][m] = (src < 0) ? 0.0f : A[src * lda + k0 + kk];
        }
        #pragma unroll
        for (int i = 0; i < 4; i++) {
            int idx = tid + i * 256;
            int n = idx >> 4, kk = idx & 15;
            Bs[kk][n] = B[(bn + n) * K + k0 + kk];
        }
        __syncthreads();

        #pragma unroll
        for (int kk = 0; kk < GBK; kk++) {
            float4 a = *reinterpret_cast<const float4*>(&As[kk][tm]);
            float4 b = *reinterpret_cast<const float4*>(&Bs[kk][tn]);
            acc[0][0] += a.x * b.x; acc[0][1] += a.x * b.y; acc[0][2] += a.x * b.z; acc[0][3] += a.x * b.w;
            acc[1][0] += a.y * b.x; acc[1][1] += a.y * b.y; acc[1][2] += a.y * b.z; acc[1][3] += a.y * b.w;
            acc[2][0] += a.z * b.x; acc[2][1] += a.z * b.y; acc[2][2] += a.z * b.z; acc[2][3] += a.z * b.w;
            acc[3][0] += a.w * b.x; acc[3][1] += a.w * b.y; acc[3][2] += a.w * b.z; acc[3][3] += a.w * b.w;
        }
        __syncthreads();
    }

    #pragma unroll
    for (int j = 0; j < 4; j++) {
        int n = bn + tn + j;
        float bb = (bias1 ? bias1[n] : 0.0f) + (bias2 ? bias2[n] : 0.0f);
        #pragma unroll
        for (int i = 0; i < 4; i++) {
            C[(bm + tm + i) * N + n] = acc[i][j] + bb;
        }
    }
}

// ---------------------------------------------------------------------------
// Persistent recurrence kernel.
// Grid (32, 4) = 128 CTAs (co-resident: 1 CTA/SM, 128 <= 148). 128 threads.
// CTA (ni, mi) owns output tile b in [32*mi, +32), n in [32*ni, +32).
// Whh slice [32n x 1024k] resident in smem as Ws[k][n] (stride 34, padded).
// h ping-pongs through g_hT0/g_hT1 in transposed layout h_T[k][b].
// Per step: stage h-tile [128k x 32b] chunks into smem (double-buffered),
// FFMA2 (fma.rn.f32x2) inner product, tanh(acc + xp), write h_T (+ states).
// ---------------------------------------------------------------------------
#define KC       128                   // k-chunk
#define NCTA     128
#define WS_STRIDE 34                   // padded row stride of Ws (even -> 8B aligned)
#define SMEM_FLOATS (DHID * WS_STRIDE + 2 * KC * 32)
#define SMEM_BYTES  (SMEM_FLOATS * 4)  // 172032 B

__device__ __forceinline__ void load_whh_slice(float* Ws, const float* __restrict__ W,
                                               int ntile, int tid)
{
    // W row-major [DHID n][DHID k]; load rows ntile..ntile+31 transposed into Ws[k][n].
    for (int idx = tid; idx < 32 * 256; idx += 128) {
        int row = idx >> 8;          // 0..31 (n local)
        int c4  = idx & 255;         // 0..255 (k/4)
        float4 v = *reinterpret_cast<const float4*>(&W[(ntile + row) * DHID + c4 * 4]);
        int k = c4 * 4;
        Ws[(k + 0) * WS_STRIDE + row] = v.x;
        Ws[(k + 1) * WS_STRIDE + row] = v.y;
        Ws[(k + 2) * WS_STRIDE + row] = v.z;
        Ws[(k + 3) * WS_STRIDE + row] = v.w;
    }
}

__device__ __forceinline__ void grid_barrier(unsigned target)
{
    __syncthreads();
    if (threadIdx.x == 0) {
        __threadfence();
        unsigned arrived = atomicAdd(&g_bar_cnt, 1u);
        if (arrived == NCTA - 1) {
            atomicExch(&g_bar_cnt, 0u);
            __threadfence();
            atomicAdd(&g_bar_phase, 1u);
        } else {
            while ((int)(atomicAdd(&g_bar_phase, 0u) - target) < 0)
                __nanosleep(40);
        }
        __threadfence();
    }
    __syncthreads();
}

__global__ void __launch_bounds__(128, 1)
rnn_persistent_kernel(const float* __restrict__ xp_enc,
                      const float* __restrict__ xp_dec,
                      const float* __restrict__ enc_Whh,
                      const float* __restrict__ dec_Whh,
                      float* __restrict__ states,
                      float* __restrict__ hT0,
                      float* __restrict__ hT1)
{
    extern __shared__ float sm[];
    float* Ws = sm;                       // [1024][34]
    float* hsb = sm + DHID * WS_STRIDE;   // 2 x [KC][32]

    const int tid = threadIdx.x;
    const int ni = blockIdx.x, mi = blockIdx.y;
    const int btile = mi * 32, ntile = ni * 32;
    const int w = tid >> 5, l = tid & 31;
    const int jj = l >> 3;                // 0..3
    const int q  = l & 7;                 // 0..7
    const int n_local = w * 8 + jj * 2;   // 2 columns
    const int b_local = q * 4;            // 4 batch rows

    // Read barrier phase baseline (uniform: no CTA can pass a barrier until all arrive).
    __shared__ unsigned s_ph;
    if (tid == 0) s_ph = atomicAdd(&g_bar_phase, 0u);

    // Zero h0 (ping buffer).
    {
        const int cta = mi * gridDim.x + ni;
        float4 z = make_float4(0.f, 0.f, 0.f, 0.f);
        *reinterpret_cast<float4*>(&hT0[cta * 1024 + tid * 8])     = z;
        *reinterpret_cast<float4*>(&hT0[cta * 1024 + tid * 8 + 4]) = z;
    }
    __syncthreads();
    unsigned target = s_ph;

    load_whh_slice(Ws, enc_Whh, ntile, tid);

    target++; grid_barrier(target);   // h0 + Whh visible everywhere

    const int rrow = tid >> 3;            // staging row base
    const int rcol = (tid & 7) * 4;       // staging col

    for (int s = 0; s < 512; s++) {
        if (s == 256) {
            load_whh_slice(Ws, dec_Whh, ntile, tid);
            __syncthreads();
        }
        const float* __restrict__ hin  = (s & 1) ? hT1 : hT0;
        float* __restrict__       hout = (s & 1) ? hT0 : hT1;
        const int t = s & 255;
        const float* __restrict__ xp = (s < 256) ? xp_enc : xp_dec;

        unsigned long long acc00 = 0ull, acc01 = 0ull, acc10 = 0ull, acc11 = 0ull;

        // Prologue: stage chunk 0.
        float4 r[8];
        #pragma unroll
        for (int i = 0; i < 8; i++)
            r[i] = *reinterpret_cast<const float4*>(&hin[(rrow + i * 16) * BSZ + btile + rcol]);
        #pragma unroll
        for (int i = 0; i < 8; i++)
            *reinterpret_cast<float4*>(&hsb[(rrow + i * 16) * 32 + rcol]) = r[i];
        __syncthreads();

        #pragma unroll 1
        for (int c = 0; c < 8; c++) {
            const int cb = c & 1;
            // Prefetch next chunk into registers (LDG latency hidden by compute).
            if (c < 7) {
                #pragma unroll
                for (int i = 0; i < 8; i++)
                    r[i] = *reinterpret_cast<const float4*>(
                        &hin[((c + 1) * KC + rrow + i * 16) * BSZ + btile + rcol]);
            }
            const float* hp = &hsb[cb * KC * 32 + b_local];
            const float* wp = &Ws[(c * KC) * WS_STRIDE + n_local];
            #pragma unroll 4
            for (int kk = 0; kk < KC; kk++) {
                float4 h4 = *reinterpret_cast<const float4*>(hp + kk * 32);
                float2 w2 = *reinterpret_cast<const float2*>(wp + kk * WS_STRIDE);
                unsigned long long h01, h23, w00, w11;
                asm("mov.b64 %0,{%1,%2};" : "=l"(h01) : "f"(h4.x), "f"(h4.y));
                asm("mov.b64 %0,{%1,%2};" : "=l"(h23) : "f"(h4.z), "f"(h4.w));
                asm("mov.b64 %0,{%1,%1};" : "=l"(w00) : "f"(w2.x));
                asm("mov.b64 %0,{%1,%1};" : "=l"(w11) : "f"(w2.y));
                asm("fma.rn.f32x2 %0,%1,%2,%0;" : "+l"(acc00) : "l"(h01), "l"(w00));
                asm("fma.rn.f32x2 %0,%1,%2,%0;" : "+l"(acc01) : "l"(h01), "l"(w11));
                asm("fma.rn.f32x2 %0,%1,%2,%0;" : "+l"(acc10) : "l"(h23), "l"(w00));
                asm("fma.rn.f32x2 %0,%1,%2,%0;" : "+l"(acc11) : "l"(h23), "l"(w11));
            }
            if (c < 7) {
                // hs[!cb] was last read in chunk c-1 (sync'ed) -> safe to overwrite.
                #pragma unroll
                for (int i = 0; i < 8; i++)
                    *reinterpret_cast<float4*>(&hsb[(1 - cb) * KC * 32 + (rrow + i * 16) * 32 + rcol]) = r[i];
                __syncthreads();
            }
        }

        // Epilogue: tanh(acc + xp), write transposed h (+ decoder states).
        float2 a[2][2];
        a[0][0] = *reinterpret_cast<float2*>(&acc00);
        a[0][1] = *reinterpret_cast<float2*>(&acc01);
        a[1][0] = *reinterpret_cast<float2*>(&acc10);
        a[1][1] = *reinterpret_cast<float2*>(&acc11);

        #pragma unroll
        for (int p = 0; p < 2; p++) {
            #pragma unroll
            for (int jn = 0; jn < 2; jn++) {
                int b0 = btile + b_local + p * 2;
                int n  = ntile + n_local + jn;
                float x0 = xp[((size_t)b0       * MAXLEN + t) * DHID + n];
                float x1 = xp[((size_t)(b0 + 1) * MAXLEN + t) * DHID + n];
                float h0 = tanhf(a[p][jn].x + x0);
                float h1 = tanhf(a[p][jn].y + x1);
                *reinterpret_cast<float2*>(&hout[n * BSZ + b0]) = make_float2(h0, h1);
                if (s >= 256) {
                    states[((size_t)b0       * MAXLEN + t) * DHID + n] = h0;
                    states[((size_t)(b0 + 1) * MAXLEN + t) * DHID + n] = h1;
                }
            }
        }

        target++; grid_barrier(target);
    }
}

// ---------------------------------------------------------------------------
// In-place row-wise log-softmax over VOC=512 columns. One warp per row.
// ---------------------------------------------------------------------------
__global__ void log_softmax_kernel(float* __restrict__ data)
{
    int gw   = (blockIdx.x * blockDim.x + threadIdx.x) >> 5;
    int lane = threadIdx.x & 31;
    if (gw >= BT) return;
    float* row = data + (size_t)gw * VOC;

    float v[16];
    float mx = -1e30f;
    #pragma unroll
    for (int i = 0; i < 16; i++) {
        v[i] = row[lane + i * 32];
        mx = fmaxf(mx, v[i]);
    }
    #pragma unroll
    for (int o = 16; o > 0; o >>= 1)
        mx = fmaxf(mx, __shfl_xor_sync(0xffffffffu, mx, o));

    float s = 0.0f;
    #pragma unroll
    for (int i = 0; i < 16; i++) s += expf(v[i] - mx);
    #pragma unroll
    for (int o = 16; o > 0; o >>= 1)
        s += __shfl_xor_sync(0xffffffffu, s, o);

    float lse = mx + logf(s);
    #pragma unroll
    for (int i = 0; i < 16; i++) row[lane + i * 32] = v[i] - lse;
}

// ---------------------------------------------------------------------------
extern "C" void kernel_launch(void* const* d_in, const int* in_sizes, int n_in,
                              void* d_out, int out_size)
{
    const int*   inputs  = (const int*)d_in[0];
    const int*   outputs = (const int*)d_in[1];
    const float* emb     = (const float*)d_in[2];
    const float* enc_Wih = (const float*)d_in[3];
    const float* enc_Whh = (const float*)d_in[4];
    const float* enc_bih = (const float*)d_in[5];
    const float* enc_bhh = (const float*)d_in[6];
    const float* dec_Wih = (const float*)d_in[7];
    const float* dec_Whh = (const float*)d_in[8];
    const float* dec_bih = (const float*)d_in[9];
    const float* dec_bhh = (const float*)d_in[10];
    const float* out_W   = (const float*)d_in[11];
    const float* out_b   = (const float*)d_in[12];
    float* out = (float*)d_out;

    float *xp_enc, *xp_dec, *states, *hT0, *hT1;
    cudaGetSymbolAddress((void**)&xp_enc, g_xp_enc);
    cudaGetSymbolAddress((void**)&xp_dec, g_xp_dec);
    cudaGetSymbolAddress((void**)&states, g_states);
    cudaGetSymbolAddress((void**)&hT0,    g_hT0);
    cudaGetSymbolAddress((void**)&hT1,    g_hT1);

    // Input projections (embedding gather fused): xp = emb[tok] @ Wih^T + bih + bhh
    gemm_gather_kernel<<<dim3(DHID / GBN, BT / GBM), 256>>>(
        emb, DCHAR, inputs, 1, MAXLEN, enc_Wih, enc_bih, enc_bhh, xp_enc, DHID, DCHAR);
    gemm_gather_kernel<<<dim3(DHID / GBN, BT / GBM), 256>>>(
        emb, DCHAR, outputs, 2, MAXLEN, dec_Wih, dec_bih, dec_bhh, xp_dec, DHID, DCHAR);

    // Persistent recurrence: encoder 256 steps + decoder 256 steps, grid-synced.
    cudaFuncSetAttribute(rnn_persistent_kernel,
                         cudaFuncAttributeMaxDynamicSharedMemorySize, SMEM_BYTES);
    rnn_persistent_kernel<<<dim3(32, 4), 128, SMEM_BYTES>>>(
        xp_enc, xp_dec, enc_Whh, dec_Whh, states, hT0, hT1);

    // logits = states @ out_W^T + out_b -> d_out, then log-softmax in place.
    gemm_gather_kernel<<<dim3(VOC / GBN, BT / GBM), 256>>>(
        states, DHID, nullptr, 0, MAXLEN, out_W, out_b, nullptr, out, VOC, DHID);

    log_softmax_kernel<<<BT / 8, 256>>>(out);
}